// round 8
// baseline (speedup 1.0000x reference)
#include <cuda_runtime.h>
#include <cuda_bf16.h>
#include <math.h>

// ------------------------------------------------------------------
// Problem constants
// ------------------------------------------------------------------
#define TT   4096
#define DD   128
#define HH   512
#define H3   1536
#define EE   256
#define WNW  4
#define NB   128          // persistent CTAs in scan (<=148 SMs -> co-resident)
#define NTH  512          // threads per scan CTA

// ------------------------------------------------------------------
// Device scratch (no cudaMalloc allowed anywhere)
// ------------------------------------------------------------------
__device__ float g_xW [TT * H3];            // x@W  + b      (25.2 MB)
__device__ float g_xWa[TT * HH];            // x@Wa + ba     ( 8.4 MB)
__device__ float g_gwX[(size_t)TT * WNW * H3];  // emb[ids]@Ww + bw (100.7 MB)
__device__ unsigned char g_mask[TT * WNW];  // canonicalized bool mask
__device__ int   g_any [TT];                // any(mask) per step
__device__ float g_cw  [WNW * HH];          // per-step c_w exchange buffer
__device__ unsigned int          g_count;   // barrier arrival counter
__device__ volatile unsigned int g_gen;     // barrier generation flag

// ------------------------------------------------------------------
// Helpers
// ------------------------------------------------------------------
__device__ __forceinline__ float wsum(float v) {
#pragma unroll
    for (int o = 16; o; o >>= 1) v += __shfl_xor_sync(0xffffffffu, v, o);
    return v;
}
__device__ __forceinline__ float sigf(float x) { return 1.0f / (1.0f + expf(-x)); }

// Sense-free grid barrier with monotonically increasing generation target.
// Release: writers' STGs happen-before bar.sync -> thread0 fence -> atomic.
// Acquire: thread0 volatile-spin -> fence -> bar.sync -> readers.
__device__ __forceinline__ void gbar(unsigned int target) {
    __syncthreads();
    if (threadIdx.x == 0) {
        __threadfence();
        unsigned int old = atomicAdd(&g_count, 1u);
        if (old == NB - 1u) {
            atomicExch(&g_count, 0u);
            __threadfence();
            g_gen = target;                  // release
        } else {
            while (g_gen < target) { }       // spin on L2 (volatile)
            __threadfence();                 // acquire
        }
    }
    __syncthreads();
}

// ------------------------------------------------------------------
// Barrier state reset (must run every launch: determinism)
// ------------------------------------------------------------------
__global__ void reset_kernel() {
    g_count = 0u;
    g_gen   = 0u;
}

// ------------------------------------------------------------------
// word_mask dtype detection + canonicalization + any() precompute.
// Hypotheses: int32 (0/1 words), float32 (0.0/1.0 words), else uint8.
// Inspect the first TT 4-byte words (16384 bytes -> in-bounds for all).
// ------------------------------------------------------------------
__global__ void mask_kernel(const unsigned char* __restrict__ raw) {
    __shared__ int s_notI32, s_notF32, s_mode;
    int tid = threadIdx.x;
    if (tid == 0) { s_notI32 = 0; s_notF32 = 0; }
    __syncthreads();

    const unsigned int* w = (const unsigned int*)raw;
    int li = 0, lf = 0;
    for (int i = tid; i < TT; i += blockDim.x) {
        unsigned int v = w[i];
        if (v != 0u && v != 1u)          li = 1;
        if (v != 0u && v != 0x3f800000u) lf = 1;
    }
    if (li) atomicOr(&s_notI32, 1);
    if (lf) atomicOr(&s_notF32, 1);
    __syncthreads();
    if (tid == 0) s_mode = (!s_notI32) ? 1 : ((!s_notF32) ? 2 : 0);
    __syncthreads();

    int mode = s_mode;
    for (int i = tid; i < TT * WNW; i += blockDim.x) {
        unsigned char m;
        if (mode == 1)      m = (((const int*)  raw)[i] != 0);
        else if (mode == 2) m = (((const float*)raw)[i] != 0.0f);
        else                m = (raw[i] != 0);
        g_mask[i] = m;
    }
    __syncthreads();
    for (int t = tid; t < TT; t += blockDim.x) {
        g_any[t] = (g_mask[4*t] | g_mask[4*t+1] | g_mask[4*t+2] | g_mask[4*t+3]) ? 1 : 0;
    }
}

// ------------------------------------------------------------------
// GEMM with optional A-row gather and bias:
//   C[M,N] = gather(A)[M,K] @ B[K,N] + bias[N]
// 128x128 tile, BK=16, 256 threads, 8x8 register microtile.
// M % 128 == 0, N % 128 == 0, K % 16 == 0 for all uses.
// ------------------------------------------------------------------
#define GBM 128
#define GBN 128
#define GBK 16
__global__ __launch_bounds__(256) void gemm_bias(
    const float* __restrict__ A, const float* __restrict__ B,
    const float* __restrict__ bias, float* __restrict__ C,
    int M, int N, int K, const int* __restrict__ gather)
{
    __shared__ float As[GBK][GBM];
    __shared__ float Bs[GBK][GBN];

    const int tid = threadIdx.x;
    const int bm0 = blockIdx.y * GBM, bn0 = blockIdx.x * GBN;
    const int tx = tid & 15, ty = tid >> 4;

    float acc[8][8];
#pragma unroll
    for (int i = 0; i < 8; i++)
#pragma unroll
        for (int j = 0; j < 8; j++) acc[i][j] = 0.0f;

    int arow[8];
#pragma unroll
    for (int i = 0; i < 8; i++) {
        int m = (tid + i * 256) >> 4;
        int r = bm0 + m;
        arow[i] = gather ? gather[r] : r;
    }

    for (int k0 = 0; k0 < K; k0 += GBK) {
#pragma unroll
        for (int i = 0; i < 8; i++) {
            int lin = tid + i * 256;
            int m = lin >> 4, kk = lin & 15;
            As[kk][m] = A[(size_t)arow[i] * K + k0 + kk];
        }
#pragma unroll
        for (int i = 0; i < 8; i++) {
            int lin = tid + i * 256;
            int kk = lin >> 7, n = lin & 127;
            Bs[kk][n] = B[(size_t)(k0 + kk) * N + bn0 + n];
        }
        __syncthreads();
#pragma unroll
        for (int kk = 0; kk < GBK; kk++) {
            float a[8], bb[8];
#pragma unroll
            for (int i = 0; i < 8; i++) a[i]  = As[kk][ty * 8 + i];
#pragma unroll
            for (int j = 0; j < 8; j++) bb[j] = Bs[kk][tx * 8 + j];
#pragma unroll
            for (int i = 0; i < 8; i++)
#pragma unroll
                for (int j = 0; j < 8; j++) acc[i][j] = fmaf(a[i], bb[j], acc[i][j]);
        }
        __syncthreads();
    }

#pragma unroll
    for (int i = 0; i < 8; i++) {
        int row = bm0 + ty * 8 + i;
#pragma unroll
        for (int j = 0; j < 8; j++) {
            int col = bn0 + tx * 8 + j;
            C[(size_t)row * N + col] = acc[i][j] + bias[col];
        }
    }
}

// ------------------------------------------------------------------
// Persistent scan kernel. 128 CTAs x 512 threads. CTA bx owns hidden
// columns j0..j0+3 (j0 = bx*4). Weight slices (U/Uw: 12 cols each,
// Ua: 4 cols) live in smem for the whole scan.
//
// Per step:
//   stage:   sh = h_{t-1};  shs/scs = out rows at word_starts
//   phase A: gates(i,o,g) for owned cols; word-cell gates -> c_w -> g_cw
//   gbar(2t+1)
//   phase B: load full c_w; alpha = sig(xWa + c_w@Ua); softmax-combine
//            -> c1, h1 -> out row t (doubles as Hbuf/Cbuf)
//   gbar(2t+2)
// ------------------------------------------------------------------
#define SMEM_FLOATS (12*512 + 12*512 + 4*512 + 512 + 3*4*512 + 12 + 16 + 4)
#define SMEM_BYTES  (SMEM_FLOATS * 4)

__global__ __launch_bounds__(NTH, 1) void scan_kernel(
    float* __restrict__ out,
    const int* __restrict__ wstarts,
    const float* __restrict__ h0,
    const float* __restrict__ c0,
    const float* __restrict__ U,
    const float* __restrict__ Uw,
    const float* __restrict__ Ua)
{
    extern __shared__ float sm[];
    float* sU      = sm;                 // [12][512]  U cols (dj*3+p)
    float* sUw     = sU   + 12*512;      // [12][512]  Uw cols
    float* sUa     = sUw  + 12*512;      // [4][512]   Ua cols
    float* sh      = sUa  + 4*512;       // [512]      h_prev
    float* shs     = sh   + 512;         // [4][512]   h at word starts
    float* scs     = shs  + 4*512;       // [4][512]   c at word starts
    float* scw     = scs  + 4*512;       // [4][512]   full c_w (phase B)
    float* s_iog   = scw  + 4*512;       // [12]       sig(i),sig(o),tanh(g) per dj
    float* s_alpha = s_iog + 12;         // [16]       alpha[w*4+dj]

    const int tid  = threadIdx.x;
    const int wg   = tid >> 5;
    const int lane = tid & 31;
    const int j0   = blockIdx.x * 4;

    // ---- one-time weight preload into smem ----
    for (int idx = tid; idx < 12 * 512; idx += NTH) {
        int p = idx >> 9, k = idx & 511;
        int dj = p / 3, which = p - dj * 3;
        int col = which * 512 + j0 + dj;
        sU[idx]  = U [(size_t)k * H3 + col];
        sUw[idx] = Uw[(size_t)k * H3 + col];
    }
    for (int idx = tid; idx < 4 * 512; idx += NTH) {
        int dj = idx >> 9, k = idx & 511;
        sUa[idx] = Ua[(size_t)k * HH + j0 + dj];
    }
    float cprev = (tid < 4) ? c0[j0 + tid] : 0.0f;   // register-carried c_{t-1}
    __syncthreads();

    for (int t = 0; t < TT; t++) {
        // ---- stage loads (all rows referenced were written in earlier steps;
        //      t==0 uses h0 and zeros, matching Hbuf/Cbuf zero-init) ----
        {
            const int k = tid;  // NTH == 512 == HH
            sh[k] = (t == 0) ? h0[k] : out[(size_t)(t - 1) * 1024 + k];
#pragma unroll
            for (int w = 0; w < WNW; w++) {
                int s = wstarts[t * WNW + w];
                size_t base = (size_t)s * 1024;
                shs[w * 512 + k] = (t == 0) ? 0.0f : out[base + k];
                scs[w * 512 + k] = (t == 0) ? 0.0f : out[base + 512 + k];
            }
        }
        __syncthreads();

        // ---- phase A: 20 triple-dot tasks over 16 warps ----
        // task 0..3  : main gates, vector = sh,       matrix = sU,  dj = task
        // task 4..19 : word gates, vector = shs[w],   matrix = sUw, w,dj
        for (int task = wg; task < 20; task += 16) {
            const float* Wm; const float* vec; int dj, w = 0; bool isU;
            if (task < 4) { isU = true;  dj = task; Wm = sU;  vec = sh; }
            else { isU = false; int q = task - 4; w = q >> 2; dj = q & 3;
                   Wm = sUw; vec = shs + w * 512; }
            const int jp = j0 + dj;

            float add0 = 0.f, add1 = 0.f, add2 = 0.f;
            if (lane == 0) {
                const float* src = isU ? (g_xW + (size_t)t * H3)
                                       : (g_gwX + (size_t)(t * WNW + w) * H3);
                add0 = src[jp]; add1 = src[512 + jp]; add2 = src[1024 + jp];
            }
            const float* m0 = Wm + (dj * 3 + 0) * 512;
            const float* m1 = Wm + (dj * 3 + 1) * 512;
            const float* m2 = Wm + (dj * 3 + 2) * 512;
            float a0 = 0.f, a1 = 0.f, a2 = 0.f;
#pragma unroll
            for (int m = 0; m < 16; m++) {
                int k = lane + (m << 5);       // stride-32: conflict-free
                float hv = vec[k];
                a0 = fmaf(hv, m0[k], a0);
                a1 = fmaf(hv, m1[k], a1);
                a2 = fmaf(hv, m2[k], a2);
            }
            a0 = wsum(a0); a1 = wsum(a1); a2 = wsum(a2);
            if (lane == 0) {
                if (isU) {
                    s_iog[dj * 3 + 0] = sigf(add0 + a0);    // i gate (sigmoided)
                    s_iog[dj * 3 + 1] = sigf(add1 + a1);    // o gate
                    s_iog[dj * 3 + 2] = tanhf(add2 + a2);   // g gate (tanh'd)
                } else {
                    // gw split order: f, i, g
                    float cwv = sigf(add0 + a0) * scs[w * 512 + jp]
                              + sigf(add1 + a1) * tanhf(add2 + a2);
                    g_cw[w * 512 + jp] = cwv;
                }
            }
        }
        gbar(2u * t + 1u);

        // ---- phase B: full c_w (L2-only loads: g_cw is re-written each step) ----
        for (int i = tid; i < WNW * 512; i += NTH)
            scw[i] = __ldcg(&g_cw[i]);
        __syncthreads();

        // alpha[w][jp] = sig(xWa[t,jp] + c_w[w] . Ua[:,jp]); 16 warps = 16 tasks
        {
            const int w = wg >> 2, dj = wg & 3;
            const int jp = j0 + dj;
            float add = (lane == 0) ? g_xWa[(size_t)t * HH + jp] : 0.f;
            const float* ua = sUa + dj * 512;
            const float* cv = scw + w * 512;
            float a = 0.f;
#pragma unroll
            for (int m = 0; m < 16; m++) {
                int k = lane + (m << 5);
                a = fmaf(cv[k], ua[k], a);
            }
            a = wsum(a);
            if (lane == 0) s_alpha[wg] = sigf(add + a);
        }
        __syncthreads();

        // ---- final combine: 4 threads, one per owned column ----
        if (tid < 4) {
            const int dj = tid, jp = j0 + dj;
            float ig = s_iog[dj * 3 + 0];
            float og = s_iog[dj * 3 + 1];
            float gg = s_iog[dj * 3 + 2];
            float e0 = expf(ig);
            float se = e0, num = e0 * gg;
#pragma unroll
            for (int w = 0; w < WNW; w++) {
                if (g_mask[t * WNW + w]) {
                    float ew = expf(s_alpha[w * 4 + dj]);
                    se += ew;
                    num = fmaf(ew, scw[w * 512 + jp], num);
                }
            }
            float c1 = g_any[t] ? (num / se)
                                : ((1.0f - ig) * cprev + ig * gg);
            float h1 = og * tanhf(c1);
            out[(size_t)t * 1024 + jp]       = h1;
            out[(size_t)t * 1024 + 512 + jp] = c1;
            cprev = c1;
        }
        gbar(2u * t + 2u);   // publish out[t] + protect g_cw reuse
    }
}

// ------------------------------------------------------------------
// Launch. Input order (metadata): x, word_ids, word_starts, word_mask,
// h0, c0, emb, W, U, b, Wa, Ua, ba, Ww, Uw, bw.  Output: [T, 2H] f32.
// ------------------------------------------------------------------
extern "C" void kernel_launch(void* const* d_in, const int* in_sizes, int n_in,
                              void* d_out, int out_size)
{
    const float*         x        = (const float*)d_in[0];
    const int*           word_ids = (const int*)  d_in[1];
    const int*           wstarts  = (const int*)  d_in[2];
    const unsigned char* mraw     = (const unsigned char*)d_in[3];
    const float*         h0       = (const float*)d_in[4];
    const float*         c0       = (const float*)d_in[5];
    const float*         emb      = (const float*)d_in[6];
    const float*         W        = (const float*)d_in[7];
    const float*         U        = (const float*)d_in[8];
    const float*         b        = (const float*)d_in[9];
    const float*         Wa       = (const float*)d_in[10];
    const float*         Ua       = (const float*)d_in[11];
    const float*         ba       = (const float*)d_in[12];
    const float*         Ww       = (const float*)d_in[13];
    const float*         Uw       = (const float*)d_in[14];
    const float*         bw       = (const float*)d_in[15];
    float*               out      = (float*)d_out;

    (void)in_sizes; (void)n_in; (void)out_size;

    // Opt into >48KB dynamic smem for the scan kernel (idempotent, immediate).
    cudaFuncSetAttribute(scan_kernel,
                         cudaFuncAttributeMaxDynamicSharedMemorySize, SMEM_BYTES);

    // Resolve device-global scratch addresses for use as kernel args.
    void *pxW = nullptr, *pxWa = nullptr, *pgwX = nullptr;
    cudaGetSymbolAddress(&pxW,  g_xW);
    cudaGetSymbolAddress(&pxWa, g_xWa);
    cudaGetSymbolAddress(&pgwX, g_gwX);

    reset_kernel<<<1, 32>>>();
    mask_kernel<<<1, 1024>>>(mraw);

    // xW  = x @ W  + b    : [4096,128]@[128,1536]
    gemm_bias<<<dim3(H3 / GBN, TT / GBM), 256>>>(
        x, W, b, (float*)pxW, TT, H3, DD, nullptr);
    // xWa = x @ Wa + ba   : [4096,128]@[128,512]
    gemm_bias<<<dim3(HH / GBN, TT / GBM), 256>>>(
        x, Wa, ba, (float*)pxWa, TT, HH, DD, nullptr);
    // gwX = emb[word_ids] @ Ww + bw : [16384,256]@[256,1536]
    gemm_bias<<<dim3(H3 / GBN, (TT * WNW) / GBM), 256>>>(
        emb, Ww, bw, (float*)pgwX, TT * WNW, H3, EE, word_ids);

    scan_kernel<<<NB, NTH, SMEM_BYTES>>>(out, wstarts, h0, c0, U, Uw, Ua);
}